// round 1
// baseline (speedup 1.0000x reference)
#include <cuda_runtime.h>
#include <math.h>
#include <stdint.h>

#define N_NODES 100000
#define N_EDGES 3200000
#define N_FEAT  512
#define N_HID   256
#define N_CLASS 40
#define K_HOPS  10

// ---------------- scratch (device globals: no allocation allowed) ----------
__device__ int   g_cnt[N_NODES];          // histogram, then scatter cursor
__device__ int   g_rowptr[N_NODES + 1];
__device__ int   g_col[N_EDGES];
__device__ float g_w[N_EDGES];
__device__ float g_x1[(size_t)N_NODES * N_HID];                  // 102.4 MB
__device__ float g_xs[(size_t)(K_HOPS + 1) * N_NODES * N_CLASS]; // 176 MB

// ---------------- CSR construction ----------------
__global__ void k_zero_cnt() {
    int i = blockIdx.x * blockDim.x + threadIdx.x;
    if (i < N_NODES) g_cnt[i] = 0;
}

__global__ void k_hist(const int* __restrict__ erow) {
    int e = blockIdx.x * blockDim.x + threadIdx.x;
    if (e < N_EDGES) atomicAdd(&g_cnt[erow[e]], 1);
}

// single-block exclusive scan of g_cnt -> g_rowptr (and reset g_cnt to cursor)
__global__ void k_scan() {
    __shared__ int warp_sums[32];
    __shared__ int s_carry;
    const int t = threadIdx.x;
    const int lane = t & 31, wid = t >> 5;
    if (t == 0) s_carry = 0;
    __syncthreads();
    for (int base = 0; base < N_NODES; base += 1024) {
        int i = base + t;
        int v = (i < N_NODES) ? g_cnt[i] : 0;
        // warp inclusive scan
        int x = v;
        #pragma unroll
        for (int d = 1; d < 32; d <<= 1) {
            int y = __shfl_up_sync(0xffffffffu, x, d);
            if (lane >= d) x += y;
        }
        if (lane == 31) warp_sums[wid] = x;
        __syncthreads();
        if (wid == 0) {
            int s = warp_sums[lane];
            #pragma unroll
            for (int d = 1; d < 32; d <<= 1) {
                int y = __shfl_up_sync(0xffffffffu, s, d);
                if (lane >= d) s += y;
            }
            warp_sums[lane] = s;
        }
        __syncthreads();
        int block_incl = x + (wid > 0 ? warp_sums[wid - 1] : 0);
        int total = warp_sums[31];
        int excl = s_carry + block_incl - v;
        if (i < N_NODES) { g_rowptr[i] = excl; g_cnt[i] = excl; }
        __syncthreads();
        if (t == 0) s_carry += total;
        __syncthreads();
    }
    if (t == 0) g_rowptr[N_NODES] = N_EDGES;
}

__global__ void k_scatter(const int* __restrict__ erow, const int* __restrict__ ecol,
                          const float* __restrict__ ew) {
    int e = blockIdx.x * blockDim.x + threadIdx.x;
    if (e < N_EDGES) {
        int r = erow[e];
        int pos = atomicAdd(&g_cnt[r], 1);
        g_col[pos] = ecol[e];
        g_w[pos]   = ew[e];
    }
}

// ---------------- tiled fp32 GEMM (+bias, optional relu) ----------------
// 256 threads, BM x BN tile, TM x TN per thread. (BM/TM)*(BN/TN) must be 256.
template <int BM, int BN, int BK, int TM, int TN, bool RELU>
__global__ __launch_bounds__(256) void k_gemm(
    const float* __restrict__ A, const float* __restrict__ B,
    const float* __restrict__ bias, float* __restrict__ C,
    int M, int N, int K)
{
    __shared__ float As[2][BK][BM];
    __shared__ float Bs[2][BK][BN];
    const int t  = threadIdx.x;
    const int m0 = blockIdx.y * BM;
    const int n0 = blockIdx.x * BN;
    constexpr int NX = BN / TN;
    const int tn = t % NX;
    const int tm = t / NX;

    auto loadA = [&](int buf, int k0) {
        #pragma unroll
        for (int idx = t; idx < BM * BK; idx += 256) {
            int r = idx / BK, c = idx % BK;
            int gr = m0 + r;
            As[buf][c][r] = (gr < M) ? A[(size_t)gr * K + (k0 + c)] : 0.f;
        }
    };
    auto loadB = [&](int buf, int k0) {
        for (int idx = t; idx < BK * BN; idx += 256) {
            int r = idx / BN, c = idx % BN;
            Bs[buf][r][c] = B[(size_t)(k0 + r) * N + (n0 + c)];
        }
    };

    loadA(0, 0);
    loadB(0, 0);
    __syncthreads();

    float acc[TM][TN];
    #pragma unroll
    for (int i = 0; i < TM; i++)
        #pragma unroll
        for (int j = 0; j < TN; j++) acc[i][j] = 0.f;

    const int NKT = K / BK;
    for (int kt = 0; kt < NKT; ++kt) {
        const int cur = kt & 1;
        if (kt + 1 < NKT) { loadA(cur ^ 1, (kt + 1) * BK); loadB(cur ^ 1, (kt + 1) * BK); }
        #pragma unroll
        for (int k = 0; k < BK; k++) {
            float a[TM], b[TN];
            if constexpr (TM % 4 == 0) {
                #pragma unroll
                for (int i = 0; i < TM; i += 4) {
                    float4 v = *(const float4*)&As[cur][k][tm * TM + i];
                    a[i] = v.x; a[i+1] = v.y; a[i+2] = v.z; a[i+3] = v.w;
                }
            } else {
                #pragma unroll
                for (int i = 0; i < TM; i++) a[i] = As[cur][k][tm * TM + i];
            }
            if constexpr (TN % 4 == 0) {
                #pragma unroll
                for (int j = 0; j < TN; j += 4) {
                    float4 v = *(const float4*)&Bs[cur][k][tn * TN + j];
                    b[j] = v.x; b[j+1] = v.y; b[j+2] = v.z; b[j+3] = v.w;
                }
            } else {
                #pragma unroll
                for (int j = 0; j < TN; j++) b[j] = Bs[cur][k][tn * TN + j];
            }
            #pragma unroll
            for (int i = 0; i < TM; i++)
                #pragma unroll
                for (int j = 0; j < TN; j++)
                    acc[i][j] += a[i] * b[j];
        }
        __syncthreads();
    }

    #pragma unroll
    for (int i = 0; i < TM; i++) {
        int gr = m0 + tm * TM + i;
        if (gr >= M) continue;
        #pragma unroll
        for (int j = 0; j < TN; j++) {
            int gc = n0 + tn * TN + j;
            float v = acc[i][j] + bias[gc];
            if (RELU) v = fmaxf(v, 0.f);
            C[(size_t)gr * N + gc] = v;
        }
    }
}

// ---------------- SpMM hop: warp per node (CSR gather) ----------------
__global__ void k_spmm(const float* __restrict__ xin, float* __restrict__ xout) {
    int gw   = (blockIdx.x * blockDim.x + threadIdx.x) >> 5;
    int lane = threadIdx.x & 31;
    if (gw >= N_NODES) return;
    int beg = g_rowptr[gw], end = g_rowptr[gw + 1];
    bool a1 = lane < (N_CLASS - 32);
    float acc0 = 0.f, acc1 = 0.f;
    int e = beg;
    for (; e + 2 <= end; e += 2) {
        int ca = g_col[e], cb = g_col[e + 1];
        float wa = g_w[e], wb = g_w[e + 1];
        const float* xa = xin + (size_t)ca * N_CLASS;
        const float* xb = xin + (size_t)cb * N_CLASS;
        acc0 += wa * xa[lane];
        acc0 += wb * xb[lane];
        if (a1) { acc1 += wa * xa[lane + 32]; acc1 += wb * xb[lane + 32]; }
    }
    if (e < end) {
        int ca = g_col[e]; float wa = g_w[e];
        const float* xa = xin + (size_t)ca * N_CLASS;
        acc0 += wa * xa[lane];
        if (a1) acc1 += wa * xa[lane + 32];
    }
    xout[(size_t)gw * N_CLASS + lane] = acc0;
    if (a1) xout[(size_t)gw * N_CLASS + lane + 32] = acc1;
}

// ---------------- attention gate + log_softmax: warp per node ----------------
__global__ void k_attn(const float* __restrict__ Wa, const float* __restrict__ ba,
                       float* __restrict__ out) {
    int gw   = (blockIdx.x * blockDim.x + threadIdx.x) >> 5;
    int lane = threadIdx.x & 31;
    if (gw >= N_NODES) return;
    int c0 = lane, c1 = lane + 32;
    bool a1 = c1 < N_CLASS;
    float wa0 = Wa[c0];
    float wa1 = a1 ? Wa[c1] : 0.f;
    float bav = ba[0];

    float v0[K_HOPS + 1], v1[K_HOPS + 1];
    #pragma unroll
    for (int k = 0; k <= K_HOPS; k++) {
        const float* x = g_xs + ((size_t)k * N_NODES + gw) * N_CLASS;
        v0[k] = x[c0];
        v1[k] = a1 ? x[c1] : 0.f;
    }
    float o0 = 0.f, o1 = 0.f;
    #pragma unroll
    for (int k = 0; k <= K_HOPS; k++) {
        float p = v0[k] * wa0 + v1[k] * wa1;
        #pragma unroll
        for (int d = 16; d; d >>= 1) p += __shfl_xor_sync(0xffffffffu, p, d);
        float s = 1.f / (1.f + expf(-(p + bav)));
        o0 += s * v0[k];
        o1 += s * v1[k];
    }
    // log_softmax over the 40 values {o0 on lanes 0..31, o1 on lanes 0..7}
    float m = o0;
    if (a1) m = fmaxf(m, o1);
    #pragma unroll
    for (int d = 16; d; d >>= 1) m = fmaxf(m, __shfl_xor_sync(0xffffffffu, m, d));
    float se = expf(o0 - m) + (a1 ? expf(o1 - m) : 0.f);
    #pragma unroll
    for (int d = 16; d; d >>= 1) se += __shfl_xor_sync(0xffffffffu, se, d);
    float ls = logf(se);
    out[(size_t)gw * N_CLASS + c0] = o0 - m - ls;
    if (a1) out[(size_t)gw * N_CLASS + c1] = o1 - m - ls;
}

// ---------------- launch ----------------
extern "C" void kernel_launch(void* const* d_in, const int* in_sizes, int n_in,
                              void* d_out, int out_size) {
    const float* feature = (const float*)d_in[0];
    const int*   erow    = (const int*)  d_in[1];
    const int*   ecol    = (const int*)  d_in[2];
    const float* ew      = (const float*)d_in[3];
    const float* W1      = (const float*)d_in[4];
    const float* b1      = (const float*)d_in[5];
    const float* W2      = (const float*)d_in[6];
    const float* b2      = (const float*)d_in[7];
    const float* Wa      = (const float*)d_in[8];
    const float* ba      = (const float*)d_in[9];
    float*       out     = (float*)d_out;

    float* x1_ptr = nullptr;
    float* xs_ptr = nullptr;
    cudaGetSymbolAddress((void**)&x1_ptr, g_x1);
    cudaGetSymbolAddress((void**)&xs_ptr, g_xs);

    // CSR build
    k_zero_cnt<<<(N_NODES + 255) / 256, 256>>>();
    k_hist<<<(N_EDGES + 255) / 256, 256>>>(erow);
    k_scan<<<1, 1024>>>();
    k_scatter<<<(N_EDGES + 255) / 256, 256>>>(erow, ecol, ew);

    // GEMM1: x1 = relu(feature @ W1 + b1)   [100000,512]x[512,256]
    {
        dim3 grid(N_HID / 64, (N_NODES + 127) / 128);
        k_gemm<128, 64, 16, 8, 4, true><<<grid, 256>>>(feature, W1, b1, x1_ptr,
                                                       N_NODES, N_HID, N_FEAT);
    }
    // GEMM2: xs[0] = x1 @ W2 + b2           [100000,256]x[256,40]
    {
        dim3 grid(1, (N_NODES + 127) / 128);
        k_gemm<128, 40, 16, 4, 5, false><<<grid, 256>>>(x1_ptr, W2, b2, xs_ptr,
                                                        N_NODES, N_CLASS, N_HID);
    }
    // K hops of SpMM
    {
        int blocks = (N_NODES * 32 + 255) / 256;
        for (int k = 0; k < K_HOPS; k++) {
            const float* xin = xs_ptr + (size_t)k * N_NODES * N_CLASS;
            float* xout      = xs_ptr + (size_t)(k + 1) * N_NODES * N_CLASS;
            k_spmm<<<blocks, 256>>>(xin, xout);
        }
    }
    // attention + log_softmax
    {
        int blocks = (N_NODES * 32 + 255) / 256;
        k_attn<<<blocks, 256>>>(Wa, ba, out);
    }
}

// round 4
// speedup vs baseline: 1.6037x; 1.6037x over previous
#include <cuda_runtime.h>
#include <cuda_bf16.h>
#include <math.h>
#include <stdint.h>

#define N_NODES 100000
#define N_EDGES 3200000
#define N_FEAT  512
#define N_HID   256
#define N_CLASS 40
#define K_HOPS  10

#define M_PAD   100096            // 782 * 128
#define M_TILES 782

static constexpr int SA = 40;     // smem row stride in halves (32 + 8 pad)

// ======================= device scratch =======================
__device__ int   g_cnt[N_NODES];
__device__ int   g_rowptr[N_NODES + 1];
__device__ int   g_col[N_EDGES];
__device__ float g_w[N_EDGES];
__device__ __nv_bfloat16 g_x1h[(size_t)M_PAD * N_HID];
__device__ __nv_bfloat16 g_x1l[(size_t)M_PAD * N_HID];
__device__ __nv_bfloat16 g_B1h[N_HID * N_FEAT];
__device__ __nv_bfloat16 g_B1l[N_HID * N_FEAT];
__device__ __nv_bfloat16 g_B2h[64 * N_HID];
__device__ __nv_bfloat16 g_B2l[64 * N_HID];
__device__ float g_xs[(size_t)(K_HOPS + 1) * N_NODES * N_CLASS];

// ======================= helpers =======================
__device__ __forceinline__ void split2(float a, float b, uint32_t& hi, uint32_t& lo) {
    __nv_bfloat16 ha = __float2bfloat16(a), hb = __float2bfloat16(b);
    __nv_bfloat16 la = __float2bfloat16(a - __bfloat162float(ha));
    __nv_bfloat16 lb = __float2bfloat16(b - __bfloat162float(hb));
    __nv_bfloat162 h; h.x = ha; h.y = hb;
    __nv_bfloat162 l; l.x = la; l.y = lb;
    hi = *reinterpret_cast<uint32_t*>(&h);
    lo = *reinterpret_cast<uint32_t*>(&l);
}

__device__ __forceinline__ void mma16816(float* d, const uint32_t* a, const uint32_t* b) {
    asm volatile(
        "mma.sync.aligned.m16n8k16.row.col.f32.bf16.bf16.f32 "
        "{%0,%1,%2,%3}, {%4,%5,%6,%7}, {%8,%9}, {%0,%1,%2,%3};\n"
        : "+f"(d[0]), "+f"(d[1]), "+f"(d[2]), "+f"(d[3])
        : "r"(a[0]), "r"(a[1]), "r"(a[2]), "r"(a[3]), "r"(b[0]), "r"(b[1]));
}

// ======================= CSR construction =======================
__global__ void k_zero_cnt() {
    int i = blockIdx.x * blockDim.x + threadIdx.x;
    if (i < N_NODES) g_cnt[i] = 0;
}
__global__ void k_hist(const int* __restrict__ erow) {
    int e = blockIdx.x * blockDim.x + threadIdx.x;
    if (e < N_EDGES) atomicAdd(&g_cnt[erow[e]], 1);
}
__global__ void k_scan() {
    __shared__ int warp_sums[32];
    __shared__ int s_carry;
    const int t = threadIdx.x;
    const int lane = t & 31, wid = t >> 5;
    if (t == 0) s_carry = 0;
    __syncthreads();
    for (int base = 0; base < N_NODES; base += 1024) {
        int i = base + t;
        int v = (i < N_NODES) ? g_cnt[i] : 0;
        int x = v;
        #pragma unroll
        for (int d = 1; d < 32; d <<= 1) {
            int y = __shfl_up_sync(0xffffffffu, x, d);
            if (lane >= d) x += y;
        }
        if (lane == 31) warp_sums[wid] = x;
        __syncthreads();
        if (wid == 0) {
            int s = warp_sums[lane];
            #pragma unroll
            for (int d = 1; d < 32; d <<= 1) {
                int y = __shfl_up_sync(0xffffffffu, s, d);
                if (lane >= d) s += y;
            }
            warp_sums[lane] = s;
        }
        __syncthreads();
        int block_incl = x + (wid > 0 ? warp_sums[wid - 1] : 0);
        int total = warp_sums[31];
        int excl = s_carry + block_incl - v;
        if (i < N_NODES) { g_rowptr[i] = excl; g_cnt[i] = excl; }
        __syncthreads();
        if (t == 0) s_carry += total;
        __syncthreads();
    }
    if (t == 0) g_rowptr[N_NODES] = N_EDGES;
}
__global__ void k_scatter(const int* __restrict__ erow, const int* __restrict__ ecol,
                          const float* __restrict__ ew) {
    int e = blockIdx.x * blockDim.x + threadIdx.x;
    if (e < N_EDGES) {
        int r = erow[e];
        int pos = atomicAdd(&g_cnt[r], 1);
        g_col[pos] = ecol[e];
        g_w[pos]   = ew[e];
    }
}

// ======================= weight prep (transpose + bf16 split) =======================
__global__ void k_prep_w1(const float* __restrict__ W1) {
    int idx = blockIdx.x * 256 + threadIdx.x;           // idx = n*512 + k
    if (idx >= N_HID * N_FEAT) return;
    int n = idx >> 9, k = idx & 511;
    float v = W1[k * N_HID + n];
    __nv_bfloat16 h = __float2bfloat16(v);
    g_B1h[idx] = h;
    g_B1l[idx] = __float2bfloat16(v - __bfloat162float(h));
}
__global__ void k_prep_w2(const float* __restrict__ W2) {
    int idx = blockIdx.x * 256 + threadIdx.x;           // idx = n*256 + k, n in [0,64)
    if (idx >= 64 * N_HID) return;
    int n = idx >> 8, k = idx & 255;
    float v = (n < N_CLASS) ? W2[k * N_CLASS + n] : 0.f;
    __nv_bfloat16 h = __float2bfloat16(v);
    g_B2h[idx] = h;
    g_B2l[idx] = __float2bfloat16(v - __bfloat162float(h));
}

// ======================= mma.sync split-bf16 GEMM =======================
// C[M, BN_total] = A[M, K_TOT] @ B^T  (B stored [n][k], K-major)
// via AhBh + AhBl + AlBh. CTA tile 128 x BN, 8 warps (warp grid 4m x 2n).
template<int BN, bool A_FP32, int K_TOT, bool RELU, bool OUT_SPLIT, int OUT_COLS>
__global__ __launch_bounds__(256, 1) void k_mma_gemm(
    const float* __restrict__ Af,
    const __nv_bfloat16* __restrict__ Ahg,
    const __nv_bfloat16* __restrict__ Alg,
    const __nv_bfloat16* __restrict__ Bhg,
    const __nv_bfloat16* __restrict__ Blg,
    const float* __restrict__ bias,
    float* __restrict__ Cf,
    __nv_bfloat16* __restrict__ Ch,
    __nv_bfloat16* __restrict__ Cl,
    int M)
{
    constexpr int NK  = K_TOT / 32;      // 32-element K chunks
    constexpr int NF  = BN / 16;         // n-frags per warp (warp covers BN/2)
    constexpr int ASZ = 128 * SA;        // halves per A buffer
    constexpr int BSZ = BN * SA;         // halves per B buffer

    extern __shared__ char smraw[];
    __nv_bfloat16* sAh = (__nv_bfloat16*)smraw;
    __nv_bfloat16* sAl = sAh + 2 * ASZ;
    __nv_bfloat16* sBh = sAl + 2 * ASZ;
    __nv_bfloat16* sBl = sBh + 2 * BSZ;

    const int tid = threadIdx.x;
    const int wid = tid >> 5, lane = tid & 31;
    const int g = lane >> 2, q = lane & 3;
    const int warp_m = wid & 3, warp_n = wid >> 2;
    const int m0 = blockIdx.y * 128, n0 = blockIdx.x * BN;

    float acc[2][NF][4];
    #pragma unroll
    for (int i = 0; i < 2; i++)
        #pragma unroll
        for (int j = 0; j < NF; j++)
            #pragma unroll
            for (int c = 0; c < 4; c++) acc[i][j][c] = 0.f;

    float arf[16];
    uint4 arh[2], arl[2];
    uint4 brh[2], brl[2];

    auto load_regs = [&](int kc) {
        const int k0 = kc * 32;
        if constexpr (A_FP32) {
            int r = tid >> 1, c0 = (tid & 1) * 16;
            bool ok = (m0 + r) < M;
            const float* src = Af + (size_t)(m0 + r) * K_TOT + k0 + c0;
            #pragma unroll
            for (int j = 0; j < 4; j++) {
                float4 v = ok ? *(const float4*)(src + 4 * j) : make_float4(0.f, 0.f, 0.f, 0.f);
                arf[4*j] = v.x; arf[4*j+1] = v.y; arf[4*j+2] = v.z; arf[4*j+3] = v.w;
            }
        } else {
            int r = tid >> 1, c0 = (tid & 1) * 16;
            const __nv_bfloat16* sh = Ahg + (size_t)(m0 + r) * K_TOT + k0 + c0;
            const __nv_bfloat16* sl = Alg + (size_t)(m0 + r) * K_TOT + k0 + c0;
            arh[0] = *(const uint4*)sh;      arh[1] = *(const uint4*)(sh + 8);
            arl[0] = *(const uint4*)sl;      arl[1] = *(const uint4*)(sl + 8);
        }
        if constexpr (BN == 128) {
            int r = n0 + (tid >> 1), c0 = (tid & 1) * 16;
            const __nv_bfloat16* sh = Bhg + (size_t)r * K_TOT + k0 + c0;
            const __nv_bfloat16* sl = Blg + (size_t)r * K_TOT + k0 + c0;
            brh[0] = *(const uint4*)sh;      brh[1] = *(const uint4*)(sh + 8);
            brl[0] = *(const uint4*)sl;      brl[1] = *(const uint4*)(sl + 8);
        } else {
            int r = n0 + (tid >> 2), c0 = (tid & 3) * 8;
            const __nv_bfloat16* sh = Bhg + (size_t)r * K_TOT + k0 + c0;
            const __nv_bfloat16* sl = Blg + (size_t)r * K_TOT + k0 + c0;
            brh[0] = *(const uint4*)sh;
            brl[0] = *(const uint4*)sl;
        }
    };

    auto store_smem = [&](int buf) {
        if constexpr (A_FP32) {
            int r = tid >> 1, c0 = (tid & 1) * 16;
            __nv_bfloat16* dh = sAh + buf * ASZ + r * SA + c0;
            __nv_bfloat16* dl = sAl + buf * ASZ + r * SA + c0;
            #pragma unroll
            for (int j = 0; j < 8; j++) {
                uint32_t h, l;
                split2(arf[2*j], arf[2*j+1], h, l);
                *(uint32_t*)(dh + 2*j) = h;
                *(uint32_t*)(dl + 2*j) = l;
            }
        } else {
            int r = tid >> 1, c0 = (tid & 1) * 16;
            __nv_bfloat16* dh = sAh + buf * ASZ + r * SA + c0;
            __nv_bfloat16* dl = sAl + buf * ASZ + r * SA + c0;
            *(uint4*)dh = arh[0];       *(uint4*)(dh + 8) = arh[1];
            *(uint4*)dl = arl[0];       *(uint4*)(dl + 8) = arl[1];
        }
        if constexpr (BN == 128) {
            int r = tid >> 1, c0 = (tid & 1) * 16;
            __nv_bfloat16* dh = sBh + buf * BSZ + r * SA + c0;
            __nv_bfloat16* dl = sBl + buf * BSZ + r * SA + c0;
            *(uint4*)dh = brh[0];       *(uint4*)(dh + 8) = brh[1];
            *(uint4*)dl = brl[0];       *(uint4*)(dl + 8) = brl[1];
        } else {
            int r = tid >> 2, c0 = (tid & 3) * 8;
            __nv_bfloat16* dh = sBh + buf * BSZ + r * SA + c0;
            __nv_bfloat16* dl = sBl + buf * BSZ + r * SA + c0;
            *(uint4*)dh = brh[0];
            *(uint4*)dl = brl[0];
        }
    };

    auto compute = [&](int buf) {
        const __nv_bfloat16* Ah = sAh + buf * ASZ;
        const __nv_bfloat16* Al = sAl + buf * ASZ;
        const __nv_bfloat16* Bh = sBh + buf * BSZ;
        const __nv_bfloat16* Bl = sBl + buf * BSZ;
        #pragma unroll
        for (int kk = 0; kk < 2; kk++) {
            uint32_t a_h[2][4], a_l[2][4];
            #pragma unroll
            for (int i = 0; i < 2; i++) {
                int base = (warp_m * 32 + i * 16 + g) * SA + kk * 16 + 2 * q;
                a_h[i][0] = *(const uint32_t*)(Ah + base);
                a_h[i][1] = *(const uint32_t*)(Ah + base + 8 * SA);
                a_h[i][2] = *(const uint32_t*)(Ah + base + 8);
                a_h[i][3] = *(const uint32_t*)(Ah + base + 8 * SA + 8);
                a_l[i][0] = *(const uint32_t*)(Al + base);
                a_l[i][1] = *(const uint32_t*)(Al + base + 8 * SA);
                a_l[i][2] = *(const uint32_t*)(Al + base + 8);
                a_l[i][3] = *(const uint32_t*)(Al + base + 8 * SA + 8);
            }
            #pragma unroll
            for (int j = 0; j < NF; j++) {
                int bb = (warp_n * NF * 8 + j * 8 + g) * SA + kk * 16 + 2 * q;
                uint32_t b_h[2] = { *(const uint32_t*)(Bh + bb), *(const uint32_t*)(Bh + bb + 8) };
                uint32_t b_l[2] = { *(const uint32_t*)(Bl + bb), *(const uint32_t*)(Bl + bb + 8) };
                #pragma unroll
                for (int i = 0; i < 2; i++) {
                    mma16816(acc[i][j], a_h[i], b_h);
                    mma16816(acc[i][j], a_h[i], b_l);
                    mma16816(acc[i][j], a_l[i], b_h);
                }
            }
        }
    };

    load_regs(0);
    store_smem(0);
    __syncthreads();
    for (int kc = 0; kc < NK; kc++) {
        if (kc + 1 < NK) load_regs(kc + 1);
        compute(kc & 1);
        if (kc + 1 < NK) store_smem((kc + 1) & 1);
        __syncthreads();
    }

    // ---- epilogue ----
    #pragma unroll
    for (int i = 0; i < 2; i++) {
        int row0 = m0 + warp_m * 32 + i * 16 + g;
        #pragma unroll
        for (int j = 0; j < NF; j++) {
            int col = n0 + warp_n * NF * 8 + j * 8 + 2 * q;
            #pragma unroll
            for (int h2 = 0; h2 < 2; h2++) {
                int row = row0 + h2 * 8;
                float v0 = acc[i][j][h2 * 2 + 0];
                float v1 = acc[i][j][h2 * 2 + 1];
                if constexpr (OUT_SPLIT) {
                    v0 += bias[col];
                    v1 += bias[col + 1];
                    if (RELU) { v0 = fmaxf(v0, 0.f); v1 = fmaxf(v1, 0.f); }
                    uint32_t hh, ll;
                    split2(v0, v1, hh, ll);
                    *(uint32_t*)(Ch + (size_t)row * N_HID + col) = hh;
                    *(uint32_t*)(Cl + (size_t)row * N_HID + col) = ll;
                } else {
                    if (row < M && col < OUT_COLS) {
                        v0 += bias[col];
                        v1 += bias[col + 1];
                        *(float2*)(Cf + (size_t)row * OUT_COLS + col) = make_float2(v0, v1);
                    }
                }
            }
        }
    }
}

// ======================= SpMM hop: warp per node (CSR gather) =======================
__global__ void k_spmm(const float* __restrict__ xin, float* __restrict__ xout) {
    int gw   = (blockIdx.x * blockDim.x + threadIdx.x) >> 5;
    int lane = threadIdx.x & 31;
    if (gw >= N_NODES) return;
    int beg = g_rowptr[gw], end = g_rowptr[gw + 1];
    bool a1 = lane < (N_CLASS - 32);
    float acc0 = 0.f, acc1 = 0.f;
    int e = beg;
    for (; e + 2 <= end; e += 2) {
        int ca = g_col[e], cb = g_col[e + 1];
        float wa = g_w[e], wb = g_w[e + 1];
        const float* xa = xin + (size_t)ca * N_CLASS;
        const float* xb = xin + (size_t)cb * N_CLASS;
        acc0 += wa * xa[lane];
        acc0 += wb * xb[lane];
        if (a1) { acc1 += wa * xa[lane + 32]; acc1 += wb * xb[lane + 32]; }
    }
    if (e < end) {
        int ca = g_col[e]; float wa = g_w[e];
        const float* xa = xin + (size_t)ca * N_CLASS;
        acc0 += wa * xa[lane];
        if (a1) acc1 += wa * xa[lane + 32];
    }
    xout[(size_t)gw * N_CLASS + lane] = acc0;
    if (a1) xout[(size_t)gw * N_CLASS + lane + 32] = acc1;
}

// ======================= attention + log_softmax =======================
__global__ void k_attn(const float* __restrict__ Wa, const float* __restrict__ ba,
                       float* __restrict__ out) {
    int gw   = (blockIdx.x * blockDim.x + threadIdx.x) >> 5;
    int lane = threadIdx.x & 31;
    if (gw >= N_NODES) return;
    int c0 = lane, c1 = lane + 32;
    bool a1 = c1 < N_CLASS;
    float wa0 = Wa[c0];
    float wa1 = a1 ? Wa[c1] : 0.f;
    float bav = ba[0];

    float v0[K_HOPS + 1], v1[K_HOPS + 1];
    #pragma unroll
    for (int k = 0; k <= K_HOPS; k++) {
        const float* x = g_xs + ((size_t)k * N_NODES + gw) * N_CLASS;
        v0[k] = x[c0];
        v1[k] = a1 ? x[c1] : 0.f;
    }
    float o0 = 0.f, o1 = 0.f;
    #pragma unroll
    for (int k = 0; k <= K_HOPS; k++) {
        float p = v0[k] * wa0 + v1[k] * wa1;
        #pragma unroll
        for (int d = 16; d; d >>= 1) p += __shfl_xor_sync(0xffffffffu, p, d);
        float s = 1.f / (1.f + expf(-(p + bav)));
        o0 += s * v0[k];
        o1 += s * v1[k];
    }
    float m = o0;
    if (a1) m = fmaxf(m, o1);
    #pragma unroll
    for (int d = 16; d; d >>= 1) m = fmaxf(m, __shfl_xor_sync(0xffffffffu, m, d));
    float se = expf(o0 - m) + (a1 ? expf(o1 - m) : 0.f);
    #pragma unroll
    for (int d = 16; d; d >>= 1) se += __shfl_xor_sync(0xffffffffu, se, d);
    float ls = logf(se);
    out[(size_t)gw * N_CLASS + c0] = o0 - m - ls;
    if (a1) out[(size_t)gw * N_CLASS + c1] = o1 - m - ls;
}

// ======================= launch =======================
extern "C" void kernel_launch(void* const* d_in, const int* in_sizes, int n_in,
                              void* d_out, int out_size) {
    const float* feature = (const float*)d_in[0];
    const int*   erow    = (const int*)  d_in[1];
    const int*   ecol    = (const int*)  d_in[2];
    const float* ew      = (const float*)d_in[3];
    const float* W1      = (const float*)d_in[4];
    const float* b1      = (const float*)d_in[5];
    const float* W2      = (const float*)d_in[6];
    const float* b2      = (const float*)d_in[7];
    const float* Wa      = (const float*)d_in[8];
    const float* ba      = (const float*)d_in[9];
    float*       out     = (float*)d_out;

    __nv_bfloat16 *x1h, *x1l, *b1h, *b1l, *b2h, *b2l;
    float* xs_ptr;
    cudaGetSymbolAddress((void**)&x1h, g_x1h);
    cudaGetSymbolAddress((void**)&x1l, g_x1l);
    cudaGetSymbolAddress((void**)&b1h, g_B1h);
    cudaGetSymbolAddress((void**)&b1l, g_B1l);
    cudaGetSymbolAddress((void**)&b2h, g_B2h);
    cudaGetSymbolAddress((void**)&b2l, g_B2l);
    cudaGetSymbolAddress((void**)&xs_ptr, g_xs);

    // ---- CSR build ----
    k_zero_cnt<<<(N_NODES + 255) / 256, 256>>>();
    k_hist<<<(N_EDGES + 255) / 256, 256>>>(erow);
    k_scan<<<1, 1024>>>();
    k_scatter<<<(N_EDGES + 255) / 256, 256>>>(erow, ecol, ew);

    // ---- weight prep ----
    k_prep_w1<<<(N_HID * N_FEAT + 255) / 256, 256>>>(W1);
    k_prep_w2<<<(64 * N_HID + 255) / 256, 256>>>(W2);

    // ---- GEMM1: x1(split bf16) = relu(feature @ W1 + b1) ----
    {
        constexpr int SMEM1 = (2 * 128 * SA * 2 + 2 * 128 * SA * 2) * 2;  // 81920 B
        auto* fn = k_mma_gemm<128, true, 512, true, true, 256>;
        cudaFuncSetAttribute(fn, cudaFuncAttributeMaxDynamicSharedMemorySize, SMEM1);
        fn<<<dim3(2, M_TILES), 256, SMEM1>>>(feature, nullptr, nullptr, b1h, b1l, b1,
                                             nullptr, x1h, x1l, N_NODES);
    }
    // ---- GEMM2: xs[0] = x1 @ W2 + b2 (N padded to 64) ----
    {
        constexpr int SMEM2 = (2 * 128 * SA * 2 + 2 * 64 * SA * 2) * 2;   // 61440 B
        auto* fn = k_mma_gemm<64, false, 256, false, false, N_CLASS>;
        cudaFuncSetAttribute(fn, cudaFuncAttributeMaxDynamicSharedMemorySize, SMEM2);
        fn<<<dim3(1, M_TILES), 256, SMEM2>>>(nullptr, x1h, x1l, b2h, b2l, b2,
                                             xs_ptr, nullptr, nullptr, N_NODES);
    }
    // ---- K hops of SpMM ----
    {
        int blocks = (N_NODES * 32 + 255) / 256;
        for (int k = 0; k < K_HOPS; k++) {
            const float* xin = xs_ptr + (size_t)k * N_NODES * N_CLASS;
            float* xout      = xs_ptr + (size_t)(k + 1) * N_NODES * N_CLASS;
            k_spmm<<<blocks, 256>>>(xin, xout);
        }
    }
    // ---- attention + log_softmax ----
    {
        int blocks = (N_NODES * 32 + 255) / 256;
        k_attn<<<blocks, 256>>>(Wa, ba, out);
    }
}

// round 5
// speedup vs baseline: 1.8185x; 1.1339x over previous
#include <cuda_runtime.h>
#include <cuda_bf16.h>
#include <math.h>
#include <stdint.h>

#define N_NODES 100000
#define N_EDGES 3200000
#define N_FEAT  512
#define N_HID   256
#define N_CLASS 40
#define K_HOPS  10

#define M_PAD   100096            // 782 * 128
#define M_TILES 782

static constexpr int SA = 40;     // smem row stride in halves (32 + 8 pad)

// ======================= device scratch =======================
__device__ int   g_cnt[N_NODES];
__device__ int   g_rowptr[N_NODES + 1];
__device__ int   g_col[N_EDGES];
__device__ float g_w[N_EDGES];
__device__ __nv_bfloat16 g_x1h[(size_t)M_PAD * N_HID];
__device__ __nv_bfloat16 g_x1l[(size_t)M_PAD * N_HID];
__device__ __nv_bfloat16 g_B1h[N_HID * N_FEAT];
__device__ __nv_bfloat16 g_B1l[N_HID * N_FEAT];
__device__ __nv_bfloat16 g_B2h[64 * N_HID];
__device__ __nv_bfloat16 g_B2l[64 * N_HID];
__device__ float g_xs[(size_t)(K_HOPS + 1) * N_NODES * N_CLASS];

// ======================= helpers =======================
__device__ __forceinline__ void split2(float a, float b, uint32_t& hi, uint32_t& lo) {
    __nv_bfloat16 ha = __float2bfloat16(a), hb = __float2bfloat16(b);
    __nv_bfloat16 la = __float2bfloat16(a - __bfloat162float(ha));
    __nv_bfloat16 lb = __float2bfloat16(b - __bfloat162float(hb));
    __nv_bfloat162 h; h.x = ha; h.y = hb;
    __nv_bfloat162 l; l.x = la; l.y = lb;
    hi = *reinterpret_cast<uint32_t*>(&h);
    lo = *reinterpret_cast<uint32_t*>(&l);
}

__device__ __forceinline__ void mma16816(float* d, const uint32_t* a, const uint32_t* b) {
    asm volatile(
        "mma.sync.aligned.m16n8k16.row.col.f32.bf16.bf16.f32 "
        "{%0,%1,%2,%3}, {%4,%5,%6,%7}, {%8,%9}, {%0,%1,%2,%3};\n"
        : "+f"(d[0]), "+f"(d[1]), "+f"(d[2]), "+f"(d[3])
        : "r"(a[0]), "r"(a[1]), "r"(a[2]), "r"(a[3]), "r"(b[0]), "r"(b[1]));
}

__device__ __forceinline__ void ldm_x4(uint32_t* r, const void* p) {
    uint32_t a = (uint32_t)__cvta_generic_to_shared(p);
    asm volatile("ldmatrix.sync.aligned.m8n8.x4.shared.b16 {%0,%1,%2,%3}, [%4];"
                 : "=r"(r[0]), "=r"(r[1]), "=r"(r[2]), "=r"(r[3]) : "r"(a));
}

__device__ __forceinline__ void cp16(void* dst_smem, const void* src) {
    uint32_t d = (uint32_t)__cvta_generic_to_shared(dst_smem);
    asm volatile("cp.async.ca.shared.global [%0], [%1], 16;" :: "r"(d), "l"(src));
}
#define CP_COMMIT() asm volatile("cp.async.commit_group;" ::: "memory")
#define CP_WAIT0()  asm volatile("cp.async.wait_group 0;" ::: "memory")

// ======================= CSR construction =======================
__global__ void k_zero_cnt() {
    int i = blockIdx.x * blockDim.x + threadIdx.x;
    if (i < N_NODES) g_cnt[i] = 0;
}
__global__ void k_hist(const int* __restrict__ erow) {
    int e = blockIdx.x * blockDim.x + threadIdx.x;
    if (e < N_EDGES) atomicAdd(&g_cnt[erow[e]], 1);
}
__global__ void k_scan() {
    __shared__ int warp_sums[32];
    __shared__ int s_carry;
    const int t = threadIdx.x;
    const int lane = t & 31, wid = t >> 5;
    if (t == 0) s_carry = 0;
    __syncthreads();
    for (int base = 0; base < N_NODES; base += 1024) {
        int i = base + t;
        int v = (i < N_NODES) ? g_cnt[i] : 0;
        int x = v;
        #pragma unroll
        for (int d = 1; d < 32; d <<= 1) {
            int y = __shfl_up_sync(0xffffffffu, x, d);
            if (lane >= d) x += y;
        }
        if (lane == 31) warp_sums[wid] = x;
        __syncthreads();
        if (wid == 0) {
            int s = warp_sums[lane];
            #pragma unroll
            for (int d = 1; d < 32; d <<= 1) {
                int y = __shfl_up_sync(0xffffffffu, s, d);
                if (lane >= d) s += y;
            }
            warp_sums[lane] = s;
        }
        __syncthreads();
        int block_incl = x + (wid > 0 ? warp_sums[wid - 1] : 0);
        int total = warp_sums[31];
        int excl = s_carry + block_incl - v;
        if (i < N_NODES) { g_rowptr[i] = excl; g_cnt[i] = excl; }
        __syncthreads();
        if (t == 0) s_carry += total;
        __syncthreads();
    }
    if (t == 0) g_rowptr[N_NODES] = N_EDGES;
}
__global__ void k_scatter(const int* __restrict__ erow, const int* __restrict__ ecol,
                          const float* __restrict__ ew) {
    int e = blockIdx.x * blockDim.x + threadIdx.x;
    if (e < N_EDGES) {
        int r = erow[e];
        int pos = atomicAdd(&g_cnt[r], 1);
        g_col[pos] = ecol[e];
        g_w[pos]   = ew[e];
    }
}

// ======================= weight prep (transpose + bf16 split) =======================
__global__ void k_prep_w1(const float* __restrict__ W1) {
    int idx = blockIdx.x * 256 + threadIdx.x;           // idx = n*512 + k
    if (idx >= N_HID * N_FEAT) return;
    int n = idx >> 9, k = idx & 511;
    float v = W1[k * N_HID + n];
    __nv_bfloat16 h = __float2bfloat16(v);
    g_B1h[idx] = h;
    g_B1l[idx] = __float2bfloat16(v - __bfloat162float(h));
}
__global__ void k_prep_w2(const float* __restrict__ W2) {
    int idx = blockIdx.x * 256 + threadIdx.x;           // idx = n*256 + k, n in [0,64)
    if (idx >= 64 * N_HID) return;
    int n = idx >> 8, k = idx & 255;
    float v = (n < N_CLASS) ? W2[k * N_CLASS + n] : 0.f;
    __nv_bfloat16 h = __float2bfloat16(v);
    g_B2h[idx] = h;
    g_B2l[idx] = __float2bfloat16(v - __bfloat162float(h));
}

// ======================= mma.sync split-bf16 GEMM (ldmatrix + cp.async) ==========
// C[M, ...] = A[M, K_TOT] @ B^T  (B stored [n][k], K-major)
// via AhBh + AhBl + AlBh. CTA tile 128 x BN, 8 warps (warp grid 4m x 2n).
template<int BN, bool A_FP32, int K_TOT, bool RELU, bool OUT_SPLIT, int OUT_COLS>
__global__ __launch_bounds__(256, 1) void k_mma_gemm(
    const float* __restrict__ Af,
    const __nv_bfloat16* __restrict__ Ahg,
    const __nv_bfloat16* __restrict__ Alg,
    const __nv_bfloat16* __restrict__ Bhg,
    const __nv_bfloat16* __restrict__ Blg,
    const float* __restrict__ bias,
    float* __restrict__ Cf,
    __nv_bfloat16* __restrict__ Ch,
    __nv_bfloat16* __restrict__ Cl,
    int M)
{
    constexpr int NK    = K_TOT / 32;    // 32-element K chunks
    constexpr int NF    = BN / 16;       // n-frags per warp (warp covers BN/2)
    constexpr int NPAIR = NF / 2;
    constexpr int ASZ   = 128 * SA;      // halves per A buffer
    constexpr int BSZ   = BN * SA;       // halves per B buffer

    extern __shared__ char smraw[];
    __nv_bfloat16* sAh = (__nv_bfloat16*)smraw;
    __nv_bfloat16* sAl = sAh + 2 * ASZ;
    __nv_bfloat16* sBh = sAl + 2 * ASZ;
    __nv_bfloat16* sBl = sBh + 2 * BSZ;

    const int tid = threadIdx.x;
    const int wid = tid >> 5, lane = tid & 31;
    const int g = lane >> 2, q = lane & 3;
    const int warp_m = wid & 3, warp_n = wid >> 2;
    const int m0 = blockIdx.y * 128, n0 = blockIdx.x * BN;

    float acc[2][NF][4];
    #pragma unroll
    for (int i = 0; i < 2; i++)
        #pragma unroll
        for (int j = 0; j < NF; j++)
            #pragma unroll
            for (int c = 0; c < 4; c++) acc[i][j][c] = 0.f;

    float arf[16];

    // A fp32 register staging (GEMM1)
    auto load_regs = [&](int kc) {
        const int k0 = kc * 32;
        int r = tid >> 1, c0 = (tid & 1) * 16;
        bool ok = (m0 + r) < M;
        const float* src = Af + (size_t)(m0 + r) * K_TOT + k0 + c0;
        #pragma unroll
        for (int j = 0; j < 4; j++) {
            float4 v = ok ? *(const float4*)(src + 4 * j) : make_float4(0.f, 0.f, 0.f, 0.f);
            arf[4*j] = v.x; arf[4*j+1] = v.y; arf[4*j+2] = v.z; arf[4*j+3] = v.w;
        }
    };
    auto store_A = [&](int buf) {
        int r = tid >> 1, c0 = (tid & 1) * 16;
        __nv_bfloat16* dh = sAh + buf * ASZ + r * SA + c0;
        __nv_bfloat16* dl = sAl + buf * ASZ + r * SA + c0;
        #pragma unroll
        for (int j = 0; j < 8; j++) {
            uint32_t h, l;
            split2(arf[2*j], arf[2*j+1], h, l);
            *(uint32_t*)(dh + 2*j) = h;
            *(uint32_t*)(dl + 2*j) = l;
        }
    };

    // cp.async loads
    auto cpA = [&](int kc, int buf) {
        const int k0 = kc * 32;
        #pragma unroll
        for (int idx = tid; idx < 128 * 4; idx += 256) {
            int r = idx >> 2, c = idx & 3;
            size_t goff = (size_t)(m0 + r) * K_TOT + k0 + c * 8;
            int soff = buf * ASZ + r * SA + c * 8;
            cp16(sAh + soff, Ahg + goff);
            cp16(sAl + soff, Alg + goff);
        }
    };
    auto cpB = [&](int kc, int buf) {
        const int k0 = kc * 32;
        #pragma unroll
        for (int idx = tid; idx < BN * 4; idx += 256) {
            int r = idx >> 2, c = idx & 3;
            size_t goff = (size_t)(n0 + r) * K_TOT + k0 + c * 8;
            int soff = buf * BSZ + r * SA + c * 8;
            cp16(sBh + soff, Bhg + goff);
            cp16(sBl + soff, Blg + goff);
        }
    };

    auto compute = [&](int buf) {
        const __nv_bfloat16* Ah = sAh + buf * ASZ;
        const __nv_bfloat16* Al = sAl + buf * ASZ;
        const __nv_bfloat16* Bh = sBh + buf * BSZ;
        const __nv_bfloat16* Bl = sBl + buf * BSZ;
        #pragma unroll
        for (int kk = 0; kk < 2; kk++) {
            uint32_t a_h[2][4], a_l[2][4];
            #pragma unroll
            for (int i = 0; i < 2; i++) {
                int aoff = (warp_m * 32 + i * 16 + (lane & 15)) * SA
                         + kk * 16 + (lane >> 4) * 8;
                ldm_x4(a_h[i], Ah + aoff);
                ldm_x4(a_l[i], Al + aoff);
            }
            #pragma unroll
            for (int p = 0; p < NPAIR; p++) {
                int boff = (warp_n * NF * 8 + p * 16 + (lane >> 4) * 8 + (lane & 7)) * SA
                         + kk * 16 + ((lane >> 3) & 1) * 8;
                uint32_t bh[4], bl[4];
                ldm_x4(bh, Bh + boff);
                ldm_x4(bl, Bl + boff);
                #pragma unroll
                for (int jj = 0; jj < 2; jj++) {
                    int j = 2 * p + jj;
                    #pragma unroll
                    for (int i = 0; i < 2; i++) {
                        mma16816(acc[i][j], a_h[i], bh + 2 * jj);
                        mma16816(acc[i][j], a_h[i], bl + 2 * jj);
                        mma16816(acc[i][j], a_l[i], bh + 2 * jj);
                    }
                }
            }
        }
    };

    // ---- prologue ----
    if constexpr (A_FP32) {
        load_regs(0);
        cpB(0, 0);
        CP_COMMIT();
        store_A(0);
    } else {
        cpA(0, 0);
        cpB(0, 0);
        CP_COMMIT();
    }
    CP_WAIT0();
    __syncthreads();

    // ---- mainloop ----
    for (int kc = 0; kc < NK; kc++) {
        const int nbuf = (kc + 1) & 1;
        if (kc + 1 < NK) {
            if constexpr (A_FP32) {
                load_regs(kc + 1);
                cpB(kc + 1, nbuf);
            } else {
                cpA(kc + 1, nbuf);
                cpB(kc + 1, nbuf);
            }
            CP_COMMIT();
        }
        compute(kc & 1);
        if (kc + 1 < NK) {
            if constexpr (A_FP32) store_A(nbuf);
            CP_WAIT0();
        }
        __syncthreads();
    }

    // ---- epilogue ----
    #pragma unroll
    for (int i = 0; i < 2; i++) {
        int row0 = m0 + warp_m * 32 + i * 16 + g;
        #pragma unroll
        for (int j = 0; j < NF; j++) {
            int col = n0 + warp_n * NF * 8 + j * 8 + 2 * q;
            #pragma unroll
            for (int h2 = 0; h2 < 2; h2++) {
                int row = row0 + h2 * 8;
                float v0 = acc[i][j][h2 * 2 + 0];
                float v1 = acc[i][j][h2 * 2 + 1];
                if constexpr (OUT_SPLIT) {
                    v0 += bias[col];
                    v1 += bias[col + 1];
                    if (RELU) { v0 = fmaxf(v0, 0.f); v1 = fmaxf(v1, 0.f); }
                    uint32_t hh, ll;
                    split2(v0, v1, hh, ll);
                    *(uint32_t*)(Ch + (size_t)row * N_HID + col) = hh;
                    *(uint32_t*)(Cl + (size_t)row * N_HID + col) = ll;
                } else {
                    if (row < M && col < OUT_COLS) {
                        v0 += bias[col];
                        v1 += bias[col + 1];
                        *(float2*)(Cf + (size_t)row * OUT_COLS + col) = make_float2(v0, v1);
                    }
                }
            }
        }
    }
}

// ======================= SpMM hop: warp per node (CSR gather) =======================
__global__ void k_spmm(const float* __restrict__ xin, float* __restrict__ xout) {
    int gw   = (blockIdx.x * blockDim.x + threadIdx.x) >> 5;
    int lane = threadIdx.x & 31;
    if (gw >= N_NODES) return;
    int beg = g_rowptr[gw], end = g_rowptr[gw + 1];
    bool a1 = lane < (N_CLASS - 32);
    float acc0 = 0.f, acc1 = 0.f;
    int e = beg;
    for (; e + 2 <= end; e += 2) {
        int ca = g_col[e], cb = g_col[e + 1];
        float wa = g_w[e], wb = g_w[e + 1];
        const float* xa = xin + (size_t)ca * N_CLASS;
        const float* xb = xin + (size_t)cb * N_CLASS;
        acc0 += wa * xa[lane];
        acc0 += wb * xb[lane];
        if (a1) { acc1 += wa * xa[lane + 32]; acc1 += wb * xb[lane + 32]; }
    }
    if (e < end) {
        int ca = g_col[e]; float wa = g_w[e];
        const float* xa = xin + (size_t)ca * N_CLASS;
        acc0 += wa * xa[lane];
        if (a1) acc1 += wa * xa[lane + 32];
    }
    xout[(size_t)gw * N_CLASS + lane] = acc0;
    if (a1) xout[(size_t)gw * N_CLASS + lane + 32] = acc1;
}

// ======================= attention + log_softmax =======================
__global__ void k_attn(const float* __restrict__ Wa, const float* __restrict__ ba,
                       float* __restrict__ out) {
    int gw   = (blockIdx.x * blockDim.x + threadIdx.x) >> 5;
    int lane = threadIdx.x & 31;
    if (gw >= N_NODES) return;
    int c0 = lane, c1 = lane + 32;
    bool a1 = c1 < N_CLASS;
    float wa0 = Wa[c0];
    float wa1 = a1 ? Wa[c1] : 0.f;
    float bav = ba[0];

    float v0[K_HOPS + 1], v1[K_HOPS + 1];
    #pragma unroll
    for (int k = 0; k <= K_HOPS; k++) {
        const float* x = g_xs + ((size_t)k * N_NODES + gw) * N_CLASS;
        v0[k] = x[c0];
        v1[k] = a1 ? x[c1] : 0.f;
    }
    float o0 = 0.f, o1 = 0.f;
    #pragma unroll
    for (int k = 0; k <= K_HOPS; k++) {
        float p = v0[k] * wa0 + v1[k] * wa1;
        #pragma unroll
        for (int d = 16; d; d >>= 1) p += __shfl_xor_sync(0xffffffffu, p, d);
        float s = 1.f / (1.f + expf(-(p + bav)));
        o0 += s * v0[k];
        o1 += s * v1[k];
    }
    float m = o0;
    if (a1) m = fmaxf(m, o1);
    #pragma unroll
    for (int d = 16; d; d >>= 1) m = fmaxf(m, __shfl_xor_sync(0xffffffffu, m, d));
    float se = expf(o0 - m) + (a1 ? expf(o1 - m) : 0.f);
    #pragma unroll
    for (int d = 16; d; d >>= 1) se += __shfl_xor_sync(0xffffffffu, se, d);
    float ls = logf(se);
    out[(size_t)gw * N_CLASS + c0] = o0 - m - ls;
    if (a1) out[(size_t)gw * N_CLASS + c1] = o1 - m - ls;
}

// ======================= launch =======================
extern "C" void kernel_launch(void* const* d_in, const int* in_sizes, int n_in,
                              void* d_out, int out_size) {
    const float* feature = (const float*)d_in[0];
    const int*   erow    = (const int*)  d_in[1];
    const int*   ecol    = (const int*)  d_in[2];
    const float* ew      = (const float*)d_in[3];
    const float* W1      = (const float*)d_in[4];
    const float* b1      = (const float*)d_in[5];
    const float* W2      = (const float*)d_in[6];
    const float* b2      = (const float*)d_in[7];
    const float* Wa      = (const float*)d_in[8];
    const float* ba      = (const float*)d_in[9];
    float*       out     = (float*)d_out;

    __nv_bfloat16 *x1h, *x1l, *b1h, *b1l, *b2h, *b2l;
    float* xs_ptr;
    cudaGetSymbolAddress((void**)&x1h, g_x1h);
    cudaGetSymbolAddress((void**)&x1l, g_x1l);
    cudaGetSymbolAddress((void**)&b1h, g_B1h);
    cudaGetSymbolAddress((void**)&b1l, g_B1l);
    cudaGetSymbolAddress((void**)&b2h, g_B2h);
    cudaGetSymbolAddress((void**)&b2l, g_B2l);
    cudaGetSymbolAddress((void**)&xs_ptr, g_xs);

    // one-time side stream + events for fork-join (handles only; same captured
    // work-graph on every call)
    static cudaStream_t s2 = nullptr;
    static cudaEvent_t evFork = nullptr, evJoin = nullptr;
    if (s2 == nullptr) {
        cudaStreamCreateWithFlags(&s2, cudaStreamNonBlocking);
        cudaEventCreateWithFlags(&evFork, cudaEventDisableTiming);
        cudaEventCreateWithFlags(&evJoin, cudaEventDisableTiming);
    }

    // ---- fork: CSR build on side stream, overlapped with GEMMs ----
    cudaEventRecord(evFork, 0);
    cudaStreamWaitEvent(s2, evFork, 0);
    k_zero_cnt<<<(N_NODES + 255) / 256, 256, 0, s2>>>();
    k_hist<<<(N_EDGES + 255) / 256, 256, 0, s2>>>(erow);
    k_scan<<<1, 1024, 0, s2>>>();
    k_scatter<<<(N_EDGES + 255) / 256, 256, 0, s2>>>(erow, ecol, ew);
    cudaEventRecord(evJoin, s2);

    // ---- weight prep (main stream) ----
    k_prep_w1<<<(N_HID * N_FEAT + 255) / 256, 256>>>(W1);
    k_prep_w2<<<(64 * N_HID + 255) / 256, 256>>>(W2);

    // ---- GEMM1: x1(split bf16) = relu(feature @ W1 + b1) ----
    {
        constexpr int SMEM1 = (2 * 128 * SA + 2 * 128 * SA) * 2 * 2;  // 81920 B
        auto* fn = k_mma_gemm<128, true, 512, true, true, 256>;
        cudaFuncSetAttribute(fn, cudaFuncAttributeMaxDynamicSharedMemorySize, SMEM1);
        fn<<<dim3(2, M_TILES), 256, SMEM1>>>(feature, nullptr, nullptr, b1h, b1l, b1,
                                             nullptr, x1h, x1l, N_NODES);
    }
    // ---- GEMM2: xs[0] = x1 @ W2 + b2 (N padded to 64) ----
    {
        constexpr int SMEM2 = (2 * 128 * SA + 2 * 64 * SA) * 2 * 2;   // 61440 B
        auto* fn = k_mma_gemm<64, false, 256, false, false, N_CLASS>;
        cudaFuncSetAttribute(fn, cudaFuncAttributeMaxDynamicSharedMemorySize, SMEM2);
        fn<<<dim3(1, M_TILES), 256, SMEM2>>>(nullptr, x1h, x1l, b2h, b2l, b2,
                                             xs_ptr, nullptr, nullptr, N_NODES);
    }

    // ---- join: hops need both GEMM2 (main) and CSR (s2) ----
    cudaStreamWaitEvent(0, evJoin, 0);

    // ---- K hops of SpMM ----
    {
        int blocks = (N_NODES * 32 + 255) / 256;
        for (int k = 0; k < K_HOPS; k++) {
            const float* xin = xs_ptr + (size_t)k * N_NODES * N_CLASS;
            float* xout      = xs_ptr + (size_t)(k + 1) * N_NODES * N_CLASS;
            k_spmm<<<blocks, 256>>>(xin, xout);
        }
    }
    // ---- attention + log_softmax ----
    {
        int blocks = (N_NODES * 32 + 255) / 256;
        k_attn<<<blocks, 256>>>(Wa, ba, out);
    }
}